// round 16
// baseline (speedup 1.0000x reference)
#include <cuda_runtime.h>
#include <cuda_bf16.h>
#include <cuda_fp8.h>
#include <cstdint>
typedef uint8_t f8;

#define Bv   1024
#define Hv   512
#define TIN  336
#define TOUT 168
#define KB0  640
#define KB1  1024
#define KBF  512
#define NCTA 128
#define NTHR 512
#define NST  5
#define ACHK 131072
#define WCHK 262144
#define FCHK 32768
#define STG_B 32768
#define SMC  (1024 + NST*STG_B)          // c-state smem offset
#define SMH  (SMC + 32768)               // h staging offset
#define DSM  (SMH + 4096)

__device__ __align__(128) f8 g_We0[(size_t)2048*KB0];
__device__ __align__(128) f8 g_We1[(size_t)2048*KB1];
__device__ __align__(128) f8 g_Wd0[(size_t)2048*KB0];
__device__ __align__(128) f8 g_Wd1[(size_t)2048*KB1];
__device__ __align__(128) f8 g_Wf1[(size_t)256*KBF];
__device__ __align__(128) f8 g_A0[(size_t)2*Bv*KB0];
__device__ __align__(128) f8 g_A1[(size_t)2*Bv*KB1];
__device__ __align__(128) f8 g_xb[(size_t)Bv*TIN*16];
__device__ __align__(128) float g_hid[Bv*256];
__device__ unsigned g_cnt = 0;
__device__ volatile unsigned g_gen = 0;

struct PS { unsigned pf, pe, nIss, nCon; };

__device__ __forceinline__ float sigf(float x) { return 1.f / (1.f + __expf(-x)); }
__device__ __forceinline__ float tanh_(float x) {
    x = fminf(fmaxf(x, -15.f), 15.f);
    float e = __expf(2.f * x);
    return (e - 1.f) / (e + 1.f);
}
__device__ __forceinline__ f8 tof8(float v) {
    return (f8)__nv_cvt_float_to_fp8(v, __NV_SATFINITE, __NV_E4M3);
}

__device__ __forceinline__ void gbar() {
    __syncthreads();
    __threadfence();
    if (threadIdx.x == 0) {
        unsigned gen = g_gen;
        if (atomicAdd(&g_cnt, 1u) == (unsigned)(gridDim.x - 1)) {
            g_cnt = 0; __threadfence(); g_gen = gen + 1;
        } else {
            while (g_gen == gen) { __nanosleep(32); }
        }
        __threadfence();
    }
    __syncthreads();
}
__device__ __forceinline__ void mbar_wait(uint32_t mbar, uint32_t parity) {
    uint32_t done = 0;
    while (!done) {
        asm volatile("{\n\t.reg .pred p;\n\t"
            "mbarrier.try_wait.parity.acquire.cta.shared::cta.b64 p, [%1], %2;\n\t"
            "selp.b32 %0,1,0,p;\n\t}" : "=r"(done) : "r"(mbar), "r"(parity) : "memory");
    }
}
__device__ __forceinline__ void mbar_arrive(uint32_t mbar) {
    asm volatile("mbarrier.arrive.release.cta.shared::cta.b64 _, [%0];" :: "r"(mbar) : "memory");
}
__device__ __forceinline__ void bulk_ld(uint32_t dst, const void* src, uint32_t bytes, uint32_t mb) {
    asm volatile("cp.async.bulk.shared::cluster.global.mbarrier::complete_tx::bytes [%0], [%1], %2, [%3];"
                 :: "r"(dst), "l"(src), "r"(bytes), "r"(mb) : "memory");
}
__device__ __forceinline__ void expect_tx(uint32_t mb, uint32_t bytes) {
    asm volatile("mbarrier.arrive.expect_tx.shared.b64 _, [%0], %1;" :: "r"(mb), "r"(bytes) : "memory");
}
__device__ __forceinline__ void ldsm4(uint32_t* r, uint32_t a) {
    asm volatile("ldmatrix.sync.aligned.m8n8.x4.shared.b16 {%0,%1,%2,%3}, [%4];"
        : "=r"(r[0]), "=r"(r[1]), "=r"(r[2]), "=r"(r[3]) : "r"(a));
}
__device__ __forceinline__ void hmma(float* c, const uint32_t* a, uint32_t b0, uint32_t b1) {
    asm volatile("mma.sync.aligned.m16n8k32.row.col.f32.e4m3.e4m3.f32 "
        "{%0,%1,%2,%3}, {%4,%5,%6,%7}, {%8,%9}, {%0,%1,%2,%3};"
        : "+f"(c[0]), "+f"(c[1]), "+f"(c[2]), "+f"(c[3])
        : "r"(a[0]), "r"(a[1]), "r"(a[2]), "r"(a[3]), "r"(b0), "r"(b1));
}
__device__ __forceinline__ uint32_t swadr(uint32_t base, int row, int colByte) {
    return base + row * 128 + (colByte ^ ((row & 7) << 4));
}
__device__ __forceinline__ void wr1(f8* base, int col, int b, f8 v) {
    base[(size_t)(col >> 7) * ACHK + b * 128 + ((col & 127) ^ ((b & 7) << 4))] = v;
}

// ---------------- cell phase ----------------
__device__ void cell_tc(char* dyn, PS& ps,
    const f8* Ag, f8* Agw, const f8* Wg, int nCh, const float* bias, float* csm,
    f8* h0d, int h0off, f8* h1d,
    f8* xdst, const f8* xsrc, int xt,
    const float* hid, const float* w2, const float* b2p, float* out, int t)
{
    const int tid = threadIdx.x, cta = blockIdx.x;
    const int b0 = (cta >> 4) * 128, u0 = (cta & 15) * 32, w0 = (cta & 15) * 128;
    uint32_t sm0 = (uint32_t)__cvta_generic_to_shared(dyn);

    if (hid != nullptr) {   // decoder cell0: pred(t-1) -> A col0 before TMA
        if (t > 0) {
            const int prow = tid >> 2, pq = tid & 3;
            const float* hr = hid + (size_t)(b0 + prow) * 256 + pq * 64;
            const float* wr = w2 + pq * 64;
            float s = 0.f;
            #pragma unroll 8
            for (int j = 0; j < 64; j++) s += __ldcg(hr + j) * __ldg(wr + j);
            s += __shfl_xor_sync(0xffffffffu, s, 1);
            s += __shfl_xor_sync(0xffffffffu, s, 2);
            float myp = fmaxf(s + __ldg(b2p), 0.f);
            if (pq == 0) {
                if ((cta & 15) == 0) out[(size_t)(b0 + prow) * TOUT + (t - 1)] = myp;
                wr1(Agw, 0, b0 + prow, tof8(myp));
            }
            __threadfence();
        }
        __syncthreads();
    }

    auto prod = [&](int kc) {
        if (tid == 0) {
            unsigned st = ps.nIss % NST;
            if (ps.nIss >= NST) { mbar_wait(sm0 + 64 + st * 8, (ps.pe >> st) & 1); ps.pe ^= 1u << st; }
            uint32_t mb = sm0 + st * 8;
            expect_tx(mb, 32768u);
            uint32_t d = sm0 + 1024 + st * STG_B;
            bulk_ld(d,         Ag + (size_t)kc * ACHK + b0 * 128, 16384u, mb);
            bulk_ld(d + 16384, Wg + (size_t)kc * WCHK + w0 * 128, 16384u, mb);
        }
        ps.nIss++;
    };
    #pragma unroll
    for (int k = 0; k < NST; k++) if (k < nCh) prod(k);

    const int lane = tid & 31, warp = tid >> 5;
    const int mi = warp >> 2, nj = warp & 3;
    const int la = lane & 15, lb = (lane >> 4) << 4;
    float acc[2][4][4];
    #pragma unroll
    for (int i = 0; i < 2; i++)
        #pragma unroll
        for (int j = 0; j < 4; j++)
            #pragma unroll
            for (int k = 0; k < 4; k++) acc[i][j][k] = 0.f;

    for (int kc = 0; kc < nCh; kc++) {
        unsigned st = ps.nCon % NST;
        mbar_wait(sm0 + st * 8, (ps.pf >> st) & 1);
        ps.pf ^= 1u << st;
        uint32_t Ab = sm0 + 1024 + st * STG_B, Bb = Ab + 16384;
        #pragma unroll
        for (int k32 = 0; k32 < 4; k32++) {
            int cb = lb + k32 * 32;
            uint32_t a0[4], a1[4], q[4];
            ldsm4(a0, swadr(Ab, mi * 32 + la, cb));
            ldsm4(a1, swadr(Ab, mi * 32 + 16 + la, cb));
            ldsm4(q, swadr(Bb, nj * 32 + la, cb));
            hmma(acc[0][0], a0, q[0], q[2]); hmma(acc[0][1], a0, q[1], q[3]);
            hmma(acc[1][0], a1, q[0], q[2]); hmma(acc[1][1], a1, q[1], q[3]);
            ldsm4(q, swadr(Bb, nj * 32 + 16 + la, cb));
            hmma(acc[0][2], a0, q[0], q[2]); hmma(acc[0][3], a0, q[1], q[3]);
            hmma(acc[1][2], a1, q[0], q[2]); hmma(acc[1][3], a1, q[1], q[3]);
        }
        if (lane == 0) mbar_arrive(sm0 + 64 + st * 8);
        ps.nCon++;
        if (NST + kc < nCh) prod(NST + kc);
    }

    // ---- epilogue: gates -> c (smem), h -> hstage (smem) ----
    f8* hst = (f8*)(dyn + SMH);
    const int qq = lane & 3, r = lane >> 2;
    #pragma unroll
    for (int im = 0; im < 2; im++)
        #pragma unroll
        for (int jn = 0; jn < 4; jn++) {
            float* c4 = acc[im][jn];
            float x0 = __shfl_xor_sync(0xffffffffu, c4[0], 1);
            float x1 = __shfl_xor_sync(0xffffffffu, c4[1], 1);
            float x2 = __shfl_xor_sync(0xffffffffu, c4[2], 1);
            float x3 = __shfl_xor_sync(0xffffffffu, c4[3], 1);
            int ul = nj * 8 + jn * 2 + (qq >> 1);
            int row; float gi, gf, gg, go;
            if ((qq & 1) == 0) { row = mi * 32 + im * 16 + r;     gi = c4[0]; gf = c4[1]; gg = x0;    go = x1; }
            else               { row = mi * 32 + im * 16 + r + 8; gi = x2;    gf = x3;    gg = c4[2]; go = c4[3]; }
            int u = u0 + ul;
            gi += __ldg(bias + u);
            gf += __ldg(bias + 512 + u);
            gg += __ldg(bias + 1024 + u);
            go += __ldg(bias + 1536 + u);
            int idx = row * 32 + ul;
            float co = csm[idx];
            float cn = sigf(gf) * co + sigf(gi) * tanh_(gg);
            float h  = sigf(go) * tanh_(cn);
            csm[idx] = cn;
            hst[idx] = tof8(h);
        }
    __syncthreads();

    // ---- coalesced h writeout: 16B per thread per destination ----
    {
        int nd = h1d ? 512 : 256;
        for (int d = tid; d < nd; d += NTHR) {
            int row = (d & 255) >> 1, seg = (d & 1) << 4;
            uint4 v = *(const uint4*)(hst + row * 32 + seg);
            f8* base; int c0;
            if (d < 256) { base = h0d; c0 = h0off + u0; }
            else         { base = h1d; c0 = u0; }
            int b = b0 + row;
            *(uint4*)(base + (size_t)(c0 >> 7) * ACHK + b * 128 +
                      (((c0 & 127) + seg) ^ ((b & 7) << 4))) = v;
        }
    }

    if (xdst && (cta & 15) == 0) {  // x cols 0..15 of next A0 buffer
        for (int i = tid; i < 128; i += NTHR) {
            int b = b0 + i;
            uint4* d = (uint4*)(xdst + (size_t)b * 128 + ((b & 7) << 4));
            if (xsrc) *d = *(const uint4*)(xsrc + ((size_t)b * TIN + xt) * 16);
            else      *d = make_uint4(0, 0, 0, 0);
        }
    }
    __syncthreads();
}

// ---------------- fc1 ----------------
__device__ void fc_phase(char* dyn, PS& ps, const float* fb1, const f8* A1rd)
{
    const int tid = threadIdx.x, cta = blockIdx.x;
    const int b0 = (cta >> 3) * 64, n0 = (cta & 7) * 32;
    const int nCh = 4;
    uint32_t sm0 = (uint32_t)__cvta_generic_to_shared(dyn);

    auto prod = [&](int kc) {
        if (tid == 0) {
            unsigned st = ps.nIss % NST;
            if (ps.nIss >= NST) { mbar_wait(sm0 + 64 + st * 8, (ps.pe >> st) & 1); ps.pe ^= 1u << st; }
            uint32_t mb = sm0 + st * 8;
            expect_tx(mb, 12288u);
            uint32_t d = sm0 + 1024 + st * STG_B;
            bulk_ld(d,        A1rd + (size_t)(4 + kc) * ACHK + b0 * 128, 8192u, mb);
            bulk_ld(d + 8192, g_Wf1 + (size_t)kc * FCHK + n0 * 128, 4096u, mb);
        }
        ps.nIss++;
    };
    #pragma unroll
    for (int k = 0; k < 4; k++) prod(k);

    const int lane = tid & 31, warp = tid >> 5;
    const int la = lane & 15, lb = (lane >> 4) << 4;
    const int mi = warp >> 1, nj = warp & 1;
    float acc[2][4];
    #pragma unroll
    for (int j = 0; j < 2; j++)
        #pragma unroll
        for (int k = 0; k < 4; k++) acc[j][k] = 0.f;

    for (int kc = 0; kc < nCh; kc++) {
        unsigned st = ps.nCon % NST;
        mbar_wait(sm0 + st * 8, (ps.pf >> st) & 1);
        ps.pf ^= 1u << st;
        if (warp < 8) {
            uint32_t Ab = sm0 + 1024 + st * STG_B, Bb = Ab + 8192;
            #pragma unroll
            for (int k32 = 0; k32 < 4; k32++) {
                int cb = lb + k32 * 32;
                uint32_t a[4], q[4];
                ldsm4(a, swadr(Ab, mi * 16 + la, cb));
                ldsm4(q, swadr(Bb, nj * 16 + la, cb));
                hmma(acc[0], a, q[0], q[2]);
                hmma(acc[1], a, q[1], q[3]);
            }
        }
        if (lane == 0) mbar_arrive(sm0 + 64 + st * 8);
        ps.nCon++;
    }
    if (warp < 8) {
        #pragma unroll
        for (int jb = 0; jb < 2; jb++) {
            int n = n0 + nj * 16 + jb * 8 + (lane & 3) * 2;
            int r0 = b0 + mi * 16 + (lane >> 2);
            g_hid[(size_t)r0 * 256 + n]           = fmaxf(acc[jb][0] + __ldg(fb1 + n), 0.f);
            g_hid[(size_t)r0 * 256 + n + 1]       = fmaxf(acc[jb][1] + __ldg(fb1 + n + 1), 0.f);
            g_hid[(size_t)(r0 + 8) * 256 + n]     = fmaxf(acc[jb][2] + __ldg(fb1 + n), 0.f);
            g_hid[(size_t)(r0 + 8) * 256 + n + 1] = fmaxf(acc[jb][3] + __ldg(fb1 + n + 1), 0.f);
        }
    }
    __syncthreads();
}

extern __shared__ __align__(1024) char dynsm[];
__global__ void __launch_bounds__(NTHR, 1) lstm_main(
    const float* eb0, const float* eb1, const float* db0, const float* db1,
    const float* fb1, const float* fW2, const float* fb2, float* out)
{
    const int tid = threadIdx.x;
    uint32_t sm0 = (uint32_t)__cvta_generic_to_shared(dynsm);
    if (tid == 0) {
        #pragma unroll
        for (int s = 0; s < NST; s++) {
            asm volatile("mbarrier.init.shared.b64 [%0], %1;" :: "r"(sm0 + s * 8), "r"(1u) : "memory");
            asm volatile("mbarrier.init.shared.b64 [%0], %1;" :: "r"(sm0 + 64 + s * 8), "r"(16u) : "memory");
        }
    }
    float* csm0 = (float*)(dynsm + SMC);
    float* csm1 = (float*)(dynsm + SMC + 16384);
    for (int i = tid; i < 8192; i += NTHR) ((float*)(dynsm + SMC))[i] = 0.f;
    __syncthreads();
    PS ps; ps.pf = 0; ps.pe = 0; ps.nIss = 0; ps.nCon = 0;
    const size_t A0SZ = (size_t)Bv * KB0, A1SZ = (size_t)Bv * KB1;

    for (int i = 0; i <= TIN; i++) {
        if (i < TIN)
            cell_tc(dynsm, ps, g_A0 + (i & 1) * A0SZ, nullptr, g_We0, 5, eb0, csm0,
                    g_A0 + ((i + 1) & 1) * A0SZ, 128, g_A1 + (i & 1) * A1SZ,
                    g_A0 + ((i + 1) & 1) * A0SZ, (i + 1 < TIN) ? g_xb : nullptr, i + 1,
                    nullptr, nullptr, nullptr, nullptr, 0);
        if (i > 0)
            cell_tc(dynsm, ps, g_A1 + ((i + 1) & 1) * A1SZ, nullptr, g_We1, 8, eb1, csm1,
                    g_A1 + (i & 1) * A1SZ, 512, nullptr,
                    nullptr, nullptr, 0, nullptr, nullptr, nullptr, nullptr, 0);
        gbar();
    }

    int p = 0, q = 0;
    for (int td = 0; td < TOUT; td++) {
        cell_tc(dynsm, ps, g_A0 + p * A0SZ, g_A0 + p * A0SZ, g_Wd0, 5, db0, csm0,
                g_A0 + (p ^ 1) * A0SZ, 128, g_A1 + q * A1SZ,
                g_A0 + (p ^ 1) * A0SZ, nullptr, 0,
                g_hid, fW2, fb2, out, td);
        gbar();
        cell_tc(dynsm, ps, g_A1 + q * A1SZ, nullptr, g_Wd1, 8, db1, csm1,
                g_A1 + (q ^ 1) * A1SZ, 512, nullptr,
                nullptr, nullptr, 0, nullptr, nullptr, nullptr, nullptr, 0);
        gbar();
        fc_phase(dynsm, ps, fb1, g_A1 + (q ^ 1) * A1SZ);
        gbar();
        p ^= 1; q ^= 1;
    }

    int gid = blockIdx.x * NTHR + tid;
    if (gid < 4096) {
        int b = gid >> 2, pq4 = gid & 3;
        const float* hr = g_hid + (size_t)b * 256 + pq4 * 64;
        const float* wr = fW2 + pq4 * 64;
        float s = 0.f;
        #pragma unroll 8
        for (int j = 0; j < 64; j++) s += __ldcg(hr + j) * __ldg(wr + j);
        s += __shfl_xor_sync(0xffffffffu, s, 1);
        s += __shfl_xor_sync(0xffffffffu, s, 2);
        if (pq4 == 0) out[(size_t)b * TOUT + 167] = fmaxf(s + __ldg(fb2), 0.f);
    }
}

// ---------------- prep ----------------
__device__ void fill_w(const float* Wih, const float* Whh, f8* dst,
                       int rows, size_t chk, int Fin, int Fpad, int Kf, int KB, int il)
{
    size_t stride = (size_t)gridDim.x * blockDim.x;
    size_t tot = (size_t)rows * KB;
    for (size_t e = (size_t)blockIdx.x * blockDim.x + threadIdx.x; e < tot; e += stride) {
        int kc = (int)(e / chk);
        int rem = (int)(e - (size_t)kc * chk);
        int rp = rem >> 7, cs = rem & 127;
        int col = kc * 128 + (cs ^ ((rp & 7) << 4));
        int g = il ? ((rp & 3) * 512 + (rp >> 2)) : rp;
        float v = 0.f;
        if (col < Fpad)      v = (col < Fin) ? Wih[(size_t)g * Fin + col] : 0.f;
        else if (col < Kf)   v = Whh[(size_t)g * Hv + (col - Fpad)];
        dst[e] = tof8(v);
    }
}

__global__ void prep_all(const float* x,
    const float* eWih0, const float* eWhh0, const float* eWih1, const float* eWhh1,
    const float* dWih0, const float* dWhh0, const float* dWih1, const float* dWhh1,
    const float* fW1)
{
    size_t stride = (size_t)gridDim.x * blockDim.x;
    size_t i0 = (size_t)blockIdx.x * blockDim.x + threadIdx.x;

    for (size_t e = i0; e < (size_t)2 * Bv * KB0; e += stride) {
        size_t pz = e / ((size_t)Bv * KB0);
        size_t i = e - pz * (size_t)Bv * KB0;
        int kc = (int)(i / ACHK);
        int rem = (int)(i - (size_t)kc * ACHK);
        int b = rem >> 7, cs = rem & 127;
        int col = kc * 128 + (cs ^ ((b & 7) << 4));
        float v = 0.f;
        if (pz == 0 && col < 16) v = x[(size_t)b * (TIN * 16) + col];
        g_A0[e] = tof8(v);
    }
    for (size_t e = i0; e < (size_t)2 * Bv * KB1; e += stride) g_A1[e] = 0;
    for (size_t e = i0; e < (size_t)Bv * TIN * 16; e += stride)
        g_xb[e] = tof8(x[e]);

    fill_w(eWih0, eWhh0, g_We0, 2048, WCHK, 16, 128, KB0, KB0, 1);
    fill_w(eWih1, eWhh1, g_We1, 2048, WCHK, 512, 512, KB1, KB1, 1);
    fill_w(dWih0, dWhh0, g_Wd0, 2048, WCHK, 1, 128, KB0, KB0, 1);
    fill_w(dWih1, dWhh1, g_Wd1, 2048, WCHK, 512, 512, KB1, KB1, 1);
    fill_w(fW1, nullptr, g_Wf1, 256, FCHK, 512, 512, KBF, KBF, 0);
}

extern "C" void kernel_launch(void* const* d_in, const int* in_sizes, int n_in,
                              void* d_out, int out_size)
{
    const float* x     = (const float*)d_in[0];
    const float* eWih0 = (const float*)d_in[1];
    const float* eWhh0 = (const float*)d_in[2];
    const float* eb0   = (const float*)d_in[3];
    const float* eWih1 = (const float*)d_in[4];
    const float* eWhh1 = (const float*)d_in[5];
    const float* eb1   = (const float*)d_in[6];
    const float* dWih0 = (const float*)d_in[7];
    const float* dWhh0 = (const float*)d_in[8];
    const float* db0   = (const float*)d_in[9];
    const float* dWih1 = (const float*)d_in[10];
    const float* dWhh1 = (const float*)d_in[11];
    const float* db1   = (const float*)d_in[12];
    const float* fW1   = (const float*)d_in[13];
    const float* fb1   = (const float*)d_in[14];
    const float* fW2   = (const float*)d_in[15];
    const float* fb2   = (const float*)d_in[16];
    float* out = (float*)d_out;

    cudaFuncSetAttribute(lstm_main, cudaFuncAttributeMaxDynamicSharedMemorySize, DSM);
    prep_all<<<512, 256>>>(x, eWih0, eWhh0, eWih1, eWhh1, dWih0, dWhh0, dWih1, dWhh1, fW1);
    lstm_main<<<NCTA, NTHR, DSM>>>(eb0, eb1, db0, db1, fb1, fW2, fb2, out);
}

// round 17
// speedup vs baseline: 1.1451x; 1.1451x over previous
#include <cuda_runtime.h>
#include <cuda_bf16.h>
#include <cstdint>
typedef __nv_bfloat16 bf16;

#define Bv   1024
#define Hv   512
#define TIN  336
#define TOUT 168
#define KB0  576
#define KB1  1024
#define KBF  512
#define NCTA 128
#define NTHR 512
#define NST  6
#define ACHK 65536
#define WCHK 131072
#define FCHK 16384
#define STG_B 32768
#define DSM (1024 + NST*STG_B)

__device__ __align__(128) bf16 g_We0[(size_t)2048*KB0];
__device__ __align__(128) bf16 g_We1[(size_t)2048*KB1];
__device__ __align__(128) bf16 g_Wd0[(size_t)2048*KB0];
__device__ __align__(128) bf16 g_Wd1[(size_t)2048*KB1];
__device__ __align__(128) bf16 g_Wf1[(size_t)256*KBF];
__device__ __align__(128) bf16 g_A0[(size_t)2*Bv*KB0];
__device__ __align__(128) bf16 g_A1[(size_t)2*Bv*KB1];
__device__ __align__(128) bf16 g_xb[(size_t)Bv*TIN*16];
__device__ __align__(128) float g_c0[Bv*Hv];
__device__ __align__(128) float g_c1[Bv*Hv];
__device__ __align__(128) float g_hid[Bv*256];
__device__ unsigned g_cntA[8*32];              // one padded line per b-group
__device__ volatile unsigned g_genA[8*32];

struct PS { unsigned pf, pe, nIss, nCon; };

__device__ __forceinline__ float sigf(float x) { return 1.f / (1.f + __expf(-x)); }

// group-local barrier: 16 CTAs of one b-group
__device__ __forceinline__ void gbar_grp(int grp) {
    __syncthreads();
    __threadfence();
    if (threadIdx.x == 0) {
        unsigned* cnt = &g_cntA[grp * 32];
        volatile unsigned* gen = &g_genA[grp * 32];
        unsigned g = *gen;
        if (atomicAdd(cnt, 1u) == 15u) {
            *cnt = 0; __threadfence(); *gen = g + 1;
        } else {
            while (*gen == g) { __nanosleep(32); }
        }
        __threadfence();
    }
    __syncthreads();
}
__device__ __forceinline__ void mbar_wait(uint32_t mbar, uint32_t parity) {
    uint32_t done = 0;
    while (!done) {
        asm volatile("{\n\t.reg .pred p;\n\t"
            "mbarrier.try_wait.parity.acquire.cta.shared::cta.b64 p, [%1], %2;\n\t"
            "selp.b32 %0,1,0,p;\n\t}" : "=r"(done) : "r"(mbar), "r"(parity) : "memory");
    }
}
__device__ __forceinline__ void mbar_arrive(uint32_t mbar) {
    asm volatile("mbarrier.arrive.release.cta.shared::cta.b64 _, [%0];" :: "r"(mbar) : "memory");
}
__device__ __forceinline__ void bulk_ld(uint32_t dst, const void* src, uint32_t bytes, uint32_t mb) {
    asm volatile("cp.async.bulk.shared::cluster.global.mbarrier::complete_tx::bytes [%0], [%1], %2, [%3];"
                 :: "r"(dst), "l"(src), "r"(bytes), "r"(mb) : "memory");
}
__device__ __forceinline__ void expect_tx(uint32_t mb, uint32_t bytes) {
    asm volatile("mbarrier.arrive.expect_tx.shared.b64 _, [%0], %1;" :: "r"(mb), "r"(bytes) : "memory");
}
__device__ __forceinline__ void ldsm4(uint32_t* r, uint32_t a) {
    asm volatile("ldmatrix.sync.aligned.m8n8.x4.shared.b16 {%0,%1,%2,%3}, [%4];"
        : "=r"(r[0]), "=r"(r[1]), "=r"(r[2]), "=r"(r[3]) : "r"(a));
}
__device__ __forceinline__ void hmma(float* c, const uint32_t* a, uint32_t b0, uint32_t b1) {
    asm volatile("mma.sync.aligned.m16n8k16.row.col.f32.bf16.bf16.f32 "
        "{%0,%1,%2,%3}, {%4,%5,%6,%7}, {%8,%9}, {%0,%1,%2,%3};"
        : "+f"(c[0]), "+f"(c[1]), "+f"(c[2]), "+f"(c[3])
        : "r"(a[0]), "r"(a[1]), "r"(a[2]), "r"(a[3]), "r"(b0), "r"(b1));
}
__device__ __forceinline__ uint32_t swadr(uint32_t base, int row, int colByte) {
    return base + row * 128 + (colByte ^ ((row & 7) << 4));
}
__device__ __forceinline__ void wr1(bf16* base, int col, int b, bf16 v) {
    base[(size_t)(col >> 6) * ACHK + b * 64 + ((col & 63) ^ ((b & 7) << 3))] = v;
}

// ---------------- cell phase ----------------
__device__ void cell_tc(char* dyn, PS& ps,
    const bf16* Ag, bf16* Agw, const bf16* Wg, int KB, const float* bias, float* cst,
    bf16* h0d, int h0off, bf16* h1d,
    bf16* xdst, const bf16* xsrc, int xt,
    const float* hid, const float* w2, const float* b2p, float* out, int t)
{
    const int tid = threadIdx.x, cta = blockIdx.x;
    const int b0 = (cta >> 4) * 128, u0 = (cta & 15) * 32, w0 = (cta & 15) * 128;
    const int nCh = KB >> 6;
    uint32_t sm0 = (uint32_t)__cvta_generic_to_shared(dyn);

    if (hid != nullptr) {   // decoder cell0: pred(t-1) -> A col0 before TMA
        if (t > 0) {
            const int prow = tid >> 2, pq = tid & 3;
            const float* hr = hid + (size_t)(b0 + prow) * 256 + pq * 64;
            const float* wr = w2 + pq * 64;
            float s = 0.f;
            #pragma unroll 8
            for (int j = 0; j < 64; j++) s += __ldcg(hr + j) * __ldg(wr + j);
            s += __shfl_xor_sync(0xffffffffu, s, 1);
            s += __shfl_xor_sync(0xffffffffu, s, 2);
            float myp = fmaxf(s + __ldg(b2p), 0.f);
            if (pq == 0) {
                if ((cta & 15) == 0) out[(size_t)(b0 + prow) * TOUT + (t - 1)] = myp;
                wr1(Agw, 0, b0 + prow, __float2bfloat16(myp));
            }
            __threadfence();
        }
        __syncthreads();
    }

    auto prod = [&](int kc) {
        if (tid == 0) {
            unsigned st = ps.nIss % NST;
            if (ps.nIss >= NST) { mbar_wait(sm0 + 64 + st * 8, (ps.pe >> st) & 1); ps.pe ^= 1u << st; }
            uint32_t mb = sm0 + st * 8;
            expect_tx(mb, 32768u);
            uint32_t d = sm0 + 1024 + st * STG_B;
            bulk_ld(d,         Ag + (size_t)kc * ACHK + b0 * 64, 16384u, mb);
            bulk_ld(d + 16384, Wg + (size_t)kc * WCHK + w0 * 64, 16384u, mb);
        }
        ps.nIss++;
    };
    #pragma unroll
    for (int k = 0; k < NST; k++) if (k < nCh) prod(k);

    const int lane = tid & 31, warp = tid >> 5;
    const int mi = warp >> 2, nj = warp & 3;
    const int la = lane & 15, lb = (lane >> 4) << 4;
    float acc[2][4][4];
    #pragma unroll
    for (int i = 0; i < 2; i++)
        #pragma unroll
        for (int j = 0; j < 4; j++)
            #pragma unroll
            for (int k = 0; k < 4; k++) acc[i][j][k] = 0.f;

    for (int kc = 0; kc < nCh; kc++) {
        unsigned st = ps.nCon % NST;
        mbar_wait(sm0 + st * 8, (ps.pf >> st) & 1);
        ps.pf ^= 1u << st;
        uint32_t Ab = sm0 + 1024 + st * STG_B, Bb = Ab + 16384;
        #pragma unroll
        for (int k16 = 0; k16 < 4; k16++) {
            int cb = lb + k16 * 32;
            uint32_t a0[4], a1[4], q[4];
            ldsm4(a0, swadr(Ab, mi * 32 + la, cb));
            ldsm4(a1, swadr(Ab, mi * 32 + 16 + la, cb));
            ldsm4(q, swadr(Bb, nj * 32 + la, cb));
            hmma(acc[0][0], a0, q[0], q[2]); hmma(acc[0][1], a0, q[1], q[3]);
            hmma(acc[1][0], a1, q[0], q[2]); hmma(acc[1][1], a1, q[1], q[3]);
            ldsm4(q, swadr(Bb, nj * 32 + 16 + la, cb));
            hmma(acc[0][2], a0, q[0], q[2]); hmma(acc[0][3], a0, q[1], q[3]);
            hmma(acc[1][2], a1, q[0], q[2]); hmma(acc[1][3], a1, q[1], q[3]);
        }
        if (lane == 0) mbar_arrive(sm0 + 64 + st * 8);
        ps.nCon++;
        if (NST + kc < nCh) prod(NST + kc);
    }

    const int qq = lane & 3, r = lane >> 2;
    #pragma unroll
    for (int im = 0; im < 2; im++)
        #pragma unroll
        for (int jn = 0; jn < 4; jn++) {
            float* c4 = acc[im][jn];
            float x0 = __shfl_xor_sync(0xffffffffu, c4[0], 1);
            float x1 = __shfl_xor_sync(0xffffffffu, c4[1], 1);
            float x2 = __shfl_xor_sync(0xffffffffu, c4[2], 1);
            float x3 = __shfl_xor_sync(0xffffffffu, c4[3], 1);
            int u = u0 + nj * 8 + jn * 2 + (qq >> 1);
            int row; float gi, gf, gg, go;
            if ((qq & 1) == 0) { row = mi * 32 + im * 16 + r;     gi = c4[0]; gf = c4[1]; gg = x0;    go = x1; }
            else               { row = mi * 32 + im * 16 + r + 8; gi = x2;    gf = x3;    gg = c4[2]; go = c4[3]; }
            int b = b0 + row;
            gi += __ldg(bias + u);
            gf += __ldg(bias + 512 + u);
            gg += __ldg(bias + 1024 + u);
            go += __ldg(bias + 1536 + u);
            float co = cst[(size_t)u * Bv + b];
            float cn = sigf(gf) * co + sigf(gi) * tanhf(gg);
            float h  = sigf(go) * tanhf(cn);
            cst[(size_t)u * Bv + b] = cn;
            bf16 hb = __float2bfloat16(h);
            wr1(h0d, h0off + u, b, hb);
            if (h1d) wr1(h1d, u, b, hb);
        }

    if (xdst && (cta & 15) == 0) {
        for (int i = tid; i < 256; i += NTHR) {
            int row = i >> 1, seg = i & 1;
            int b = b0 + row;
            uint4* d = (uint4*)(xdst + (size_t)b * 64 + ((seg * 8) ^ ((b & 7) << 3)));
            if (xsrc) *d = *(const uint4*)(xsrc + ((size_t)b * TIN + xt) * 16 + seg * 8);
            else      *d = make_uint4(0, 0, 0, 0);
        }
    }
}

// ---------------- fc1: group-local mapping (16 CTAs cover the group's 128 rows) ----
__device__ void fc_phase(char* dyn, PS& ps, const float* fb1, const bf16* A1rd)
{
    const int tid = threadIdx.x, cta = blockIdx.x;
    const int b0 = (cta >> 4) * 128 + ((cta >> 3) & 1) * 64;
    const int n0 = (cta & 7) * 32;
    const int nCh = 8;
    uint32_t sm0 = (uint32_t)__cvta_generic_to_shared(dyn);

    auto prod = [&](int kc) {
        if (tid == 0) {
            unsigned st = ps.nIss % NST;
            if (ps.nIss >= NST) { mbar_wait(sm0 + 64 + st * 8, (ps.pe >> st) & 1); ps.pe ^= 1u << st; }
            uint32_t mb = sm0 + st * 8;
            expect_tx(mb, 12288u);
            uint32_t d = sm0 + 1024 + st * STG_B;
            bulk_ld(d,        A1rd + (size_t)(8 + kc) * ACHK + b0 * 64, 8192u, mb);
            bulk_ld(d + 8192, g_Wf1 + (size_t)kc * FCHK + n0 * 64, 4096u, mb);
        }
        ps.nIss++;
    };
    #pragma unroll
    for (int k = 0; k < NST; k++) if (k < nCh) prod(k);

    const int lane = tid & 31, warp = tid >> 5;
    const int la = lane & 15, lb = (lane >> 4) << 4;
    const int mi = warp >> 1, nj = warp & 1;
    float acc[2][4];
    #pragma unroll
    for (int j = 0; j < 2; j++)
        #pragma unroll
        for (int k = 0; k < 4; k++) acc[j][k] = 0.f;

    for (int kc = 0; kc < nCh; kc++) {
        unsigned st = ps.nCon % NST;
        mbar_wait(sm0 + st * 8, (ps.pf >> st) & 1);
        ps.pf ^= 1u << st;
        if (warp < 8) {
            uint32_t Ab = sm0 + 1024 + st * STG_B, Bb = Ab + 8192;
            #pragma unroll
            for (int k16 = 0; k16 < 4; k16++) {
                int cb = lb + k16 * 32;
                uint32_t a[4], q[4];
                ldsm4(a, swadr(Ab, mi * 16 + la, cb));
                ldsm4(q, swadr(Bb, nj * 16 + la, cb));
                hmma(acc[0], a, q[0], q[2]);
                hmma(acc[1], a, q[1], q[3]);
            }
        }
        if (lane == 0) mbar_arrive(sm0 + 64 + st * 8);
        ps.nCon++;
        if (NST + kc < nCh) prod(NST + kc);
    }
    if (warp < 8) {
        #pragma unroll
        for (int jb = 0; jb < 2; jb++) {
            int n = n0 + nj * 16 + jb * 8 + (lane & 3) * 2;
            int r0 = b0 + mi * 16 + (lane >> 2);
            g_hid[(size_t)r0 * 256 + n]           = fmaxf(acc[jb][0] + __ldg(fb1 + n), 0.f);
            g_hid[(size_t)r0 * 256 + n + 1]       = fmaxf(acc[jb][1] + __ldg(fb1 + n + 1), 0.f);
            g_hid[(size_t)(r0 + 8) * 256 + n]     = fmaxf(acc[jb][2] + __ldg(fb1 + n), 0.f);
            g_hid[(size_t)(r0 + 8) * 256 + n + 1] = fmaxf(acc[jb][3] + __ldg(fb1 + n + 1), 0.f);
        }
    }
}

extern __shared__ __align__(1024) char dynsm[];
__global__ void __launch_bounds__(NTHR, 1) lstm_main(
    const float* eb0, const float* eb1, const float* db0, const float* db1,
    const float* fb1, const float* fW2, const float* fb2, float* out)
{
    const int tid = threadIdx.x, cta = blockIdx.x;
    const int grp = cta >> 4;
    uint32_t sm0 = (uint32_t)__cvta_generic_to_shared(dynsm);
    if (tid == 0) {
        #pragma unroll
        for (int s = 0; s < NST; s++) {
            asm volatile("mbarrier.init.shared.b64 [%0], %1;" :: "r"(sm0 + s * 8), "r"(1u) : "memory");
            asm volatile("mbarrier.init.shared.b64 [%0], %1;" :: "r"(sm0 + 64 + s * 8), "r"(16u) : "memory");
        }
    }
    __syncthreads();
    PS ps; ps.pf = 0; ps.pe = 0; ps.nIss = 0; ps.nCon = 0;
    const size_t A0SZ = (size_t)Bv * KB0, A1SZ = (size_t)Bv * KB1;

    for (int i = 0; i <= TIN; i++) {
        if (i < TIN)
            cell_tc(dynsm, ps, g_A0 + (i & 1) * A0SZ, nullptr, g_We0, KB0, eb0, g_c0,
                    g_A0 + ((i + 1) & 1) * A0SZ, 16, g_A1 + (i & 1) * A1SZ,
                    g_A0 + ((i + 1) & 1) * A0SZ, (i + 1 < TIN) ? g_xb : nullptr, i + 1,
                    nullptr, nullptr, nullptr, nullptr, 0);
        if (i > 0)
            cell_tc(dynsm, ps, g_A1 + ((i + 1) & 1) * A1SZ, nullptr, g_We1, KB1, eb1, g_c1,
                    g_A1 + (i & 1) * A1SZ, 512, nullptr,
                    nullptr, nullptr, 0, nullptr, nullptr, nullptr, nullptr, 0);
        gbar_grp(grp);
    }

    int p = 0, q = 0;
    for (int td = 0; td < TOUT; td++) {
        cell_tc(dynsm, ps, g_A0 + p * A0SZ, g_A0 + p * A0SZ, g_Wd0, KB0, db0, g_c0,
                g_A0 + (p ^ 1) * A0SZ, 16, g_A1 + q * A1SZ,
                g_A0 + (p ^ 1) * A0SZ, nullptr, 0,
                g_hid, fW2, fb2, out, td);
        gbar_grp(grp);
        cell_tc(dynsm, ps, g_A1 + q * A1SZ, nullptr, g_Wd1, KB1, db1, g_c1,
                g_A1 + (q ^ 1) * A1SZ, 512, nullptr,
                nullptr, nullptr, 0, nullptr, nullptr, nullptr, nullptr, 0);
        gbar_grp(grp);
        fc_phase(dynsm, ps, fb1, g_A1 + (q ^ 1) * A1SZ);
        gbar_grp(grp);
        p ^= 1; q ^= 1;
    }

    // final pred t=167: group-local (each CTA handles 8 of its group's 128 rows)
    if (tid < 32) {
        int b = (cta >> 4) * 128 + (cta & 15) * 8 + (tid >> 2);
        int pq4 = tid & 3;
        const float* hr = g_hid + (size_t)b * 256 + pq4 * 64;
        const float* wr = fW2 + pq4 * 64;
        float s = 0.f;
        #pragma unroll 8
        for (int j = 0; j < 64; j++) s += __ldcg(hr + j) * __ldg(wr + j);
        s += __shfl_xor_sync(0xffffffffu, s, 1);
        s += __shfl_xor_sync(0xffffffffu, s, 2);
        if (pq4 == 0) out[(size_t)b * TOUT + 167] = fmaxf(s + __ldg(fb2), 0.f);
    }
}

// ---------------- prep ----------------
__device__ void fill_w(const float* Wih, const float* Whh, bf16* dst,
                       int rows, size_t chk, int Fin, int Fpad, int Kf, int KB, int il)
{
    size_t stride = (size_t)gridDim.x * blockDim.x;
    size_t tot = (size_t)rows * KB;
    for (size_t e = (size_t)blockIdx.x * blockDim.x + threadIdx.x; e < tot; e += stride) {
        int kc = (int)(e / chk);
        int rem = (int)(e - (size_t)kc * chk);
        int rp = rem >> 6, cs = rem & 63;
        int col = kc * 64 + (cs ^ ((rp & 7) << 3));
        int g = il ? ((rp & 3) * 512 + (rp >> 2)) : rp;
        float v = 0.f;
        if (col < Fpad)      v = (col < Fin) ? Wih[(size_t)g * Fin + col] : 0.f;
        else if (col < Kf)   v = Whh[(size_t)g * Hv + (col - Fpad)];
        dst[e] = __float2bfloat16(v);
    }
}

__global__ void prep_all(const float* x,
    const float* eWih0, const float* eWhh0, const float* eWih1, const float* eWhh1,
    const float* dWih0, const float* dWhh0, const float* dWih1, const float* dWhh1,
    const float* fW1)
{
    size_t stride = (size_t)gridDim.x * blockDim.x;
    size_t i0 = (size_t)blockIdx.x * blockDim.x + threadIdx.x;

    for (size_t e = i0; e < (size_t)2 * Bv * KB0; e += stride) {
        size_t pz = e / ((size_t)Bv * KB0);
        size_t i = e - pz * (size_t)Bv * KB0;
        int kc = (int)(i / ACHK);
        int rem = (int)(i - (size_t)kc * ACHK);
        int b = rem >> 6, cs = rem & 63;
        int col = kc * 64 + (cs ^ ((b & 7) << 3));
        float v = 0.f;
        if (pz == 0 && col < 16) v = x[(size_t)b * (TIN * 16) + col];
        g_A0[e] = __float2bfloat16(v);
    }
    for (size_t e = i0; e < (size_t)2 * Bv * KB1; e += stride) g_A1[e] = __float2bfloat16(0.f);
    for (size_t e = i0; e < (size_t)Bv * Hv; e += stride) { g_c0[e] = 0.f; g_c1[e] = 0.f; }
    for (size_t e = i0; e < (size_t)Bv * TIN * 16; e += stride)
        g_xb[e] = __float2bfloat16(x[e]);

    fill_w(eWih0, eWhh0, g_We0, 2048, WCHK, 16, 16, 528, KB0, 1);
    fill_w(eWih1, eWhh1, g_We1, 2048, WCHK, 512, 512, 1024, KB1, 1);
    fill_w(dWih0, dWhh0, g_Wd0, 2048, WCHK, 1, 16, 528, KB0, 1);
    fill_w(dWih1, dWhh1, g_Wd1, 2048, WCHK, 512, 512, 1024, KB1, 1);
    fill_w(fW1, nullptr, g_Wf1, 256, FCHK, 512, 512, 512, KBF, 0);
}

extern "C" void kernel_launch(void* const* d_in, const int* in_sizes, int n_in,
                              void* d_out, int out_size)
{
    const float* x     = (const float*)d_in[0];
    const float* eWih0 = (const float*)d_in[1];
    const float* eWhh0 = (const float*)d_in[2];
    const float* eb0   = (const float*)d_in[3];
    const float* eWih1 = (const float*)d_in[4];
    const float* eWhh1 = (const float*)d_in[5];
    const float* eb1   = (const float*)d_in[6];
    const float* dWih0 = (const float*)d_in[7];
    const float* dWhh0 = (const float*)d_in[8];
    const float* db0   = (const float*)d_in[9];
    const float* dWih1 = (const float*)d_in[10];
    const float* dWhh1 = (const float*)d_in[11];
    const float* db1   = (const float*)d_in[12];
    const float* fW1   = (const float*)d_in[13];
    const float* fb1   = (const float*)d_in[14];
    const float* fW2   = (const float*)d_in[15];
    const float* fb2   = (const float*)d_in[16];
    float* out = (float*)d_out;

    cudaFuncSetAttribute(lstm_main, cudaFuncAttributeMaxDynamicSharedMemorySize, DSM);
    prep_all<<<512, 256>>>(x, eWih0, eWhh0, eWih1, eWhh1, dWih0, dWhh0, dWih1, dWhh1, fW1);
    lstm_main<<<NCTA, NTHR, DSM>>>(eb0, eb1, db0, db1, fb1, fW2, fb2, out);
}